// round 14
// baseline (speedup 1.0000x reference)
#include <cuda_runtime.h>
#include <math.h>

#define NB 16
#define NT 2048
#define ND 512
#define NC 20
#define KE 40
#define KH 20
#define FEPS 1e-5f
#define LN2F 0.69314718055994531f
#define NDB 740   // distill grid (5 blocks/SM on 148 SMs) — R9-proven optimum

// ---------------- scratch (write-only slots, no zeroing needed) ----------------
__device__ int    g_idx[NB][4][KE];     // 0=easy_act,1=easy_bkg,2=hard_act,3=hard_bkg
__device__ float  g_klp[NB][8][2];      // per (b, qchunk): [0]=p hard_act, [1]=p hard_bkg
__device__ double g_dpart[NDB];         // distill per-block partials
__device__ float  g_opart[NC];          // ortho per-row partial sums of squares

// ---------------- helpers ----------------
__device__ __forceinline__ float warp_sum(float v) {
#pragma unroll
    for (int o = 16; o; o >>= 1) v += __shfl_down_sync(0xffffffffu, v, o);
    return v;
}
__device__ __forceinline__ float warp_max(float v) {
#pragma unroll
    for (int o = 16; o; o >>= 1) v = fmaxf(v, __shfl_down_sync(0xffffffffu, v, o));
    return v;
}
__device__ __forceinline__ double warp_dsum(double v) {
#pragma unroll
    for (int o = 16; o; o >>= 1) v += __shfl_down_sync(0xffffffffu, v, o);
    return v;
}
__device__ __forceinline__ unsigned long long pk2(float lo, float hi) {
    unsigned long long r;
    asm("mov.b64 %0, {%1, %2};" : "=l"(r) : "f"(lo), "f"(hi));
    return r;
}
__device__ __forceinline__ float2 upk2(unsigned long long v) {
    float2 f;
    asm("mov.b64 {%0, %1}, %2;" : "=f"(f.x), "=f"(f.y) : "l"(v));
    return f;
}
__device__ __forceinline__ unsigned long long ffma2(unsigned long long a,
                                                   unsigned long long b,
                                                   unsigned long long c) {
    unsigned long long d;
    asm("fma.rn.f32x2 %0, %1, %2, %3;" : "=l"(d) : "l"(a), "l"(b), "l"(c));
    return d;
}

// Descending radix select: bit pattern of the value at rank k (0-indexed desc).
__device__ unsigned radix_select_desc(const float* sc, int n, int k,
                                      unsigned* hist, unsigned* shc) {
    const int tid = threadIdx.x, nthr = blockDim.x;
    unsigned prefix = 0, pmask = 0;
#pragma unroll
    for (int level = 0; level < 4; ++level) {
        const int shift = 24 - 8 * level;
        for (int i = tid; i < 256; i += nthr) hist[i] = 0;
        __syncthreads();
        for (int i = tid; i < n; i += nthr) {
            unsigned u = __float_as_uint(sc[i]);
            bool ok = ((u & pmask) == prefix);
            unsigned d = ok ? ((u >> shift) & 255u) : 0x100u;
            unsigned mm = __match_any_sync(0xffffffffu, d);
            if (ok && ((tid & 31) == __ffs(mm) - 1))
                atomicAdd(&hist[d], (unsigned)__popc(mm));
        }
        __syncthreads();
        if (tid < 32) {
            const int l = tid;
            unsigned c[8]; unsigned lsum = 0;
#pragma unroll
            for (int i = 0; i < 8; ++i) { c[i] = hist[l * 8 + i]; lsum += c[i]; }
            unsigned v = lsum;
#pragma unroll
            for (int off = 1; off < 32; off <<= 1) {
                unsigned t = __shfl_down_sync(0xffffffffu, v, off);
                if (l + off < 32) v += t;
            }
            unsigned cum = v - lsum;          // elements in higher bins
            int found = -1; unsigned nk = 0;
#pragma unroll
            for (int i = 7; i >= 0; --i) {
                if (found < 0 && (unsigned)k >= cum && (unsigned)k < cum + c[i]) {
                    found = l * 8 + i; nk = (unsigned)k - cum;
                }
                cum += c[i];
            }
            if (found >= 0) { shc[0] = (unsigned)found; shc[1] = nk; }
        }
        __syncthreads();
        prefix |= shc[0] << shift;
        pmask  |= 0xFFu << shift;
        k = (int)shc[1];
        __syncthreads();
    }
    return prefix;
}

// ---------------- kernels ----------------
__global__ void __launch_bounds__(512) k_topk(const float* __restrict__ attn,
                                              const float* __restrict__ dmask) {
    __shared__ float sa[NT];
    __shared__ float ss[NT];
    __shared__ unsigned char sab[NT];
    __shared__ unsigned hist[256];
    __shared__ unsigned shc[2];
    __shared__ unsigned bm[NT / 32];
    __shared__ unsigned pfx[NT / 32];
    __shared__ float red[16];
    __shared__ int s_cnt;
    __shared__ int s_cntGE;
    __shared__ float s_maxLess;
    const int s = blockIdx.x, b = blockIdx.y, tid = threadIdx.x;
    const int warp = tid >> 5, lane = tid & 31;

    float lmax = 0.f;
    for (int t = tid; t < NT; t += 512) {
        float v = attn[b * NT + t];
        sa[t] = v;
        lmax = fmaxf(lmax, v);
    }
    lmax = warp_max(lmax);
    if (lane == 0) red[warp] = lmax;
    if (tid == 0) { s_cntGE = 0; s_maxLess = 0.f; }
    __syncthreads();
    float amax = red[0];
#pragma unroll
    for (int w = 1; w < 16; ++w) amax = fmaxf(amax, red[w]);

    if (s >= 2) {
        unsigned v1u = radix_select_desc(sa, NT, 1023, hist, shc);
        const float v1 = __uint_as_float(v1u);
        int cnt = 0; float ml = 0.f;
        for (int t = tid; t < NT; t += 512) {
            float x = sa[t];
            if (x >= v1) ++cnt; else ml = fmaxf(ml, x);
        }
#pragma unroll
        for (int o = 16; o; o >>= 1) {
            cnt += __shfl_down_sync(0xffffffffu, cnt, o);
            ml = fmaxf(ml, __shfl_down_sync(0xffffffffu, ml, o));
        }
        if (lane == 0) {
            atomicAdd(&s_cntGE, cnt);
            atomicMax((int*)&s_maxLess, __float_as_int(ml));   // floats >= 0
        }
        __syncthreads();
        float v2 = (s_cntGE >= 1025) ? v1 : s_maxLess;
        float med = 0.5f * (v1 + v2);
        for (int t = tid; t < NT; t += 512) sab[t] = (sa[t] > med) ? 1 : 0;
        __syncthreads();
    }

    for (int t = tid; t < NT; t += 512) {
        float a = sa[t];
        float v;
        if (s == 0) v = a * dmask[b * NT + t];
        else if (s == 1) v = (amax - a) * dmask[b * NT + t];
        else {
            int bm3 = (t >= 3) ? (int)sab[t - 3] : 0;
            int bm2 = (t >= 2) ? (int)sab[t - 2] : 0;
            int bm1 = (t >= 1) ? (int)sab[t - 1] : 0;
            int b0  = (int)sab[t];
            int bp1 = (t + 1 < NT) ? (int)sab[t + 1] : 0;
            int bp2 = (t + 2 < NT) ? (int)sab[t + 2] : 0;
            int bp3 = (t + 3 < NT) ? (int)sab[t + 3] : 0;
            if (s == 2) {
                int er3 = bm1 & b0 & bp1;
                int er7 = er3 & bm3 & bm2 & bp2 & bp3;
                v = a * (float)(er3 & (er7 ^ 1));
            } else {
                int dl3 = bm1 | b0 | bp1;
                int dl7 = dl3 | bm3 | bm2 | bp2 | bp3;
                v = a * (float)(dl7 & (dl3 ^ 1));
            }
        }
        ss[t] = v;
    }
    if (tid == 0) s_cnt = 0;
    for (int i = tid; i < NT / 32; i += 512) bm[i] = 0;
    __syncthreads();
    const int K = (s < 2) ? KE : KH;
    unsigned vk = radix_select_desc(ss, NT, K - 1, hist, shc);
    const float fvk = __uint_as_float(vk);
    for (int t = tid; t < NT; t += 512) {
        float v = ss[t];
        if (v > fvk) {
            int p = atomicAdd(&s_cnt, 1);
            g_idx[b][s][p] = t;
        } else if (v == fvk) {
            atomicOr(&bm[t >> 5], 1u << (t & 31));
        }
    }
    __syncthreads();
    if (tid < 32) {
        const int l = tid;
        unsigned p0 = __popc(bm[2 * l]), p1 = __popc(bm[2 * l + 1]);
        unsigned ls = p0 + p1, v = ls;
#pragma unroll
        for (int off = 1; off < 32; off <<= 1) {
            unsigned t2 = __shfl_up_sync(0xffffffffu, v, off);
            if (l >= off) v += t2;
        }
        unsigned excl = v - ls;
        pfx[2 * l] = excl;
        pfx[2 * l + 1] = excl + p0;
    }
    __syncthreads();
    const int base = s_cnt;
    const int m = K - base;
    for (int t = tid; t < NT; t += 512) {
        if (ss[t] == fvk) {
            int r = (int)(pfx[t >> 5] + __popc(bm[t >> 5] & ((1u << (t & 31)) - 1u)));
            if (r < m) g_idx[b][s][base + r] = t;
        }
    }
}

// grid (8, NB): blockIdx.x = qs*4 + qquarter (10 q-rows each). 640 thr = 20 warps.
// R9-proven shape — frozen.
__global__ void __launch_bounds__(640, 1) k_kl(const float* __restrict__ mu,
                                               const float* __restrict__ var) {
    extern __shared__ float sm[];
    float* r_q = sm;              // [10][ND]
    float* s_q = sm + 10 * ND;    // [10][ND]
    __shared__ float Dq[10];
    __shared__ float sAct[20], sBkg[20];
    const int qs = blockIdx.x >> 2;
    const int qq = blockIdx.x & 3;
    const int b  = blockIdx.y;
    const int warp = threadIdx.x >> 5;   // 0..19
    const int lane = threadIdx.x & 31;

    unsigned long long up[2][8], wp[2][8];
    float halfLp[2];
#pragma unroll
    for (int rr = 0; rr < 2; ++rr) {
        const int idx = g_idx[b][2 + rr][warp];
        const float4* mrow = (const float4*)(mu  + ((size_t)(b * NT + idx)) * ND);
        const float4* vrow = (const float4*)(var + ((size_t)(b * NT + idx)) * ND);
        float lsum = 0.f;
#pragma unroll
        for (int it = 0; it < 4; ++it) {
            int f = lane + it * 32;
            float4 m4 = mrow[f], v4 = vrow[f];
            v4.x += FEPS; v4.y += FEPS; v4.z += FEPS; v4.w += FEPS;
            up[rr][2 * it]     = pk2(m4.x * m4.x + v4.x, m4.y * m4.y + v4.y);
            up[rr][2 * it + 1] = pk2(m4.z * m4.z + v4.z, m4.w * m4.w + v4.w);
            wp[rr][2 * it]     = pk2(-2.f * m4.x, -2.f * m4.y);
            wp[rr][2 * it + 1] = pk2(-2.f * m4.z, -2.f * m4.w);
            lsum += __log2f(v4.x) + __log2f(v4.y) + __log2f(v4.z) + __log2f(v4.w);
        }
        lsum = warp_sum(lsum);
        halfLp[rr] = 0.5f * LN2F * __shfl_sync(0xffffffffu, lsum, 0);
    }

    if (warp < 10) {
        const int j = warp;
        const int idx = g_idx[b][qs][qq * 10 + j];
        const float4* mrow = (const float4*)(mu  + ((size_t)(b * NT + idx)) * ND);
        const float4* vrow = (const float4*)(var + ((size_t)(b * NT + idx)) * ND);
        float lsum = 0.f, asum = 0.f;
#pragma unroll
        for (int it = 0; it < 4; ++it) {
            int f = lane + it * 32;
            float4 m4 = mrow[f], v4 = vrow[f];
            v4.x += FEPS; v4.y += FEPS; v4.z += FEPS; v4.w += FEPS;
            float4 r4 = make_float4(1.f / v4.x, 1.f / v4.y, 1.f / v4.z, 1.f / v4.w);
            float4 s4 = make_float4(m4.x * r4.x, m4.y * r4.y, m4.z * r4.z, m4.w * r4.w);
            ((float4*)(r_q + j * ND))[f] = r4;
            ((float4*)(s_q + j * ND))[f] = s4;
            lsum += __log2f(v4.x) + __log2f(v4.y) + __log2f(v4.z) + __log2f(v4.w);
            asum += m4.x * s4.x + m4.y * s4.y + m4.z * s4.z + m4.w * s4.w;
        }
        float red2 = warp_sum(asum + LN2F * lsum);
        if (lane == 0) Dq[j] = 0.5f * red2;
    }
    __syncthreads();

    float accinv[2] = {0.f, 0.f};
#pragma unroll 2
    for (int j = 0; j < 10; ++j) {
        const ulonglong2* rq2 = (const ulonglong2*)(r_q + j * ND);
        const ulonglong2* sq2 = (const ulonglong2*)(s_q + j * ND);
        unsigned long long aU0 = 0, aW0 = 0, aU1 = 0, aW1 = 0;
#pragma unroll
        for (int it = 0; it < 4; ++it) {
            ulonglong2 r2 = rq2[lane + it * 32];
            ulonglong2 s2 = sq2[lane + it * 32];
            aU0 = ffma2(up[0][2 * it],     r2.x, aU0);
            aU0 = ffma2(up[0][2 * it + 1], r2.y, aU0);
            aW0 = ffma2(wp[0][2 * it],     s2.x, aW0);
            aW0 = ffma2(wp[0][2 * it + 1], s2.y, aW0);
            aU1 = ffma2(up[1][2 * it],     r2.x, aU1);
            aU1 = ffma2(up[1][2 * it + 1], r2.y, aU1);
            aW1 = ffma2(wp[1][2 * it],     s2.x, aW1);
            aW1 = ffma2(wp[1][2 * it + 1], s2.y, aW1);
        }
        float2 u0 = upk2(aU0), w0 = upk2(aW0);
        float2 u1 = upk2(aU1), w1 = upk2(aW1);
        float v0 = u0.x + u0.y + w0.x + w0.y;
        float v1 = u1.x + u1.y + w1.x + w1.y;
#pragma unroll
        for (int o = 16; o; o >>= 1) {
            v0 += __shfl_down_sync(0xffffffffu, v0, o);
            v1 += __shfl_down_sync(0xffffffffu, v1, o);
        }
        if (lane == 0) {
            float d0 = 0.5f * v0 + Dq[j] - halfLp[0] - 0.5f * (float)ND;
            float d1 = 0.5f * v1 + Dq[j] - halfLp[1] - 0.5f * (float)ND;
            accinv[0] += 1.f / (d0 + 1.f);
            accinv[1] += 1.f / (d1 + 1.f);
        }
    }
    if (lane == 0) { sAct[warp] = accinv[0]; sBkg[warp] = accinv[1]; }
    __syncthreads();
    if (warp == 0) {
        float va = (lane < 20) ? sAct[lane] : 0.f;
        float vb = (lane < 20) ? sBkg[lane] : 0.f;
        va = warp_sum(va);
        vb = warp_sum(vb);
        if (lane == 0) {
            g_klp[b][blockIdx.x][0] = va;
            g_klp[b][blockIdx.x][1] = vb;
        }
    }
}

// persistent grid-stride distill (grid=NDB, 5 blocks/SM): R9-proven optimum.
// Warp processes row pairs (row, row+16384).
__global__ void __launch_bounds__(256) k_distill(const float* __restrict__ mu,
                                                 const float* __restrict__ mc) {
    const int lane = threadIdx.x & 31;
    const int wib  = threadIdx.x >> 5;
    const int gw   = blockIdx.x * 8 + wib;
    const int nw   = gridDim.x * 8;
    double local = 0.0;
    for (int row = gw; row < 16384; row += nw) {
        const size_t r0 = (size_t)row * ND;
        const size_t r1 = (size_t)(row + 16384) * ND;
        const float4* a0 = (const float4*)(mu + r0);
        const float4* c0 = (const float4*)(mc + r0);
        const float4* a1 = (const float4*)(mu + r1);
        const float4* c1 = (const float4*)(mc + r1);
        float d0 = 0.f, p0 = 0.f, q0 = 0.f;
        float d1 = 0.f, p1 = 0.f, q1 = 0.f;
#pragma unroll
        for (int it = 0; it < 4; ++it) {
            int f = lane + it * 32;
            float4 x0 = __ldcs(&a0[f]);
            float4 y0 = __ldcs(&c0[f]);
            float4 x1 = __ldcs(&a1[f]);
            float4 y1 = __ldcs(&c1[f]);
            d0 += x0.x * y0.x + x0.y * y0.y + x0.z * y0.z + x0.w * y0.w;
            p0 += x0.x * x0.x + x0.y * x0.y + x0.z * x0.z + x0.w * x0.w;
            q0 += y0.x * y0.x + y0.y * y0.y + y0.z * y0.z + y0.w * y0.w;
            d1 += x1.x * y1.x + x1.y * y1.y + x1.z * y1.z + x1.w * y1.w;
            p1 += x1.x * x1.x + x1.y * x1.y + x1.z * x1.z + x1.w * x1.w;
            q1 += y1.x * y1.x + y1.y * y1.y + y1.z * y1.z + y1.w * y1.w;
        }
#pragma unroll
        for (int o = 16; o; o >>= 1) {
            d0 += __shfl_down_sync(0xffffffffu, d0, o);
            p0 += __shfl_down_sync(0xffffffffu, p0, o);
            q0 += __shfl_down_sync(0xffffffffu, q0, o);
            d1 += __shfl_down_sync(0xffffffffu, d1, o);
            p1 += __shfl_down_sync(0xffffffffu, p1, o);
            q1 += __shfl_down_sync(0xffffffffu, q1, o);
        }
        if (lane == 0) {
            float s0 = d0 / (fmaxf(sqrtf(p0), 1e-12f) * fmaxf(sqrtf(q0), 1e-12f));
            float s1 = d1 / (fmaxf(sqrtf(p1), 1e-12f) * fmaxf(sqrtf(q1), 1e-12f));
            local += (double)((s0 + 1.f) * 0.5f) + (double)((s1 + 1.f) * 0.5f);
        }
    }
    __shared__ double bs[8];
    if (lane == 0) bs[wib] = local;
    __syncthreads();
    if (threadIdx.x == 0) {
        double s = 0.0;
        for (int w = 0; w < 8; ++w) s += bs[w];
        g_dpart[blockIdx.x] = s;
    }
}

// grid 20, 256 thr: block i computes sum_j (sim(i,j) - delta_ij)^2 -> g_opart[i]
__global__ void __launch_bounds__(256) k_ortho(const float* __restrict__ tf) {
    __shared__ float e[NC * ND];
    __shared__ float inv_n[NC];
    __shared__ float part[8];
    const int i = blockIdx.x;
    const int tid = threadIdx.x;
    const int warp = tid >> 5, lane = tid & 31;
    for (int k = tid; k < NC * (ND / 4); k += 256)
        ((float4*)e)[k] = ((const float4*)tf)[k];
    __syncthreads();
    for (int r = warp; r < NC; r += 8) {
        const float4* er = (const float4*)(e + r * ND);
        float4 acc = make_float4(0.f, 0.f, 0.f, 0.f);
#pragma unroll
        for (int it = 0; it < 4; ++it) {
            float4 v = er[lane + it * 32];
            acc.x += v.x * v.x; acc.y += v.y * v.y;
            acc.z += v.z * v.z; acc.w += v.w * v.w;
        }
        float s = warp_sum(acc.x + acc.y + acc.z + acc.w);
        if (lane == 0) inv_n[r] = 1.f / fmaxf(sqrtf(s), 1e-12f);
    }
    __syncthreads();
    const float4* ei = (const float4*)(e + i * ND);
    float accp = 0.f;
    for (int j = warp; j < NC; j += 8) {
        const float4* ej = (const float4*)(e + j * ND);
        float4 acc = make_float4(0.f, 0.f, 0.f, 0.f);
#pragma unroll
        for (int it = 0; it < 4; ++it) {
            int f = lane + it * 32;
            float4 x = ei[f], y = ej[f];
            acc.x += x.x * y.x; acc.y += x.y * y.y;
            acc.z += x.z * y.z; acc.w += x.w * y.w;
        }
        float s = warp_sum(acc.x + acc.y + acc.z + acc.w);
        if (lane == 0) {
            float m = s * inv_n[i] * inv_n[j] - ((i == j) ? 1.f : 0.f);
            accp += m * m;
        }
    }
    if (lane == 0) part[warp] = accp;
    __syncthreads();
    if (tid == 0) {
        float s = 0.f;
        for (int w = 0; w < 8; ++w) s += part[w];
        g_opart[i] = s;
    }
}

// single block scalar finalization
__global__ void __launch_bounds__(256) k_fin(float* __restrict__ out, int out_size) {
    __shared__ double dpartial[8];
    const int tid = threadIdx.x;
    const int warp = tid >> 5, lane = tid & 31;
    double dl = 0.0;
#pragma unroll
    for (int i = 0; i < 3; ++i) {
        int idx = tid + i * 256;
        if (idx < NDB) dl += g_dpart[idx];
    }
    dl = warp_dsum(dl);
    if (lane == 0) dpartial[warp] = dl;
    __syncthreads();
    if (tid == 0) {
        double ds = 0.0;
        for (int w = 0; w < 8; ++w) ds += dpartial[w];
        float distill = -logf((float)(ds / (double)(NB * NT)));
        float os = 0.f;
        for (int i = 0; i < NC; ++i) os += g_opart[i];
        float ortho = sqrtf(os);
        const float inv_pairs = 1.f / (float)(KH * KE);
        float act = 0.f, bkg = 0.f;
        for (int b = 0; b < NB; ++b) {
            float c0 = 0.f, c1 = 0.f, c2 = 0.f, c3 = 0.f;
            for (int x = 0; x < 4; ++x) { c0 += g_klp[b][x][0]; c3 += g_klp[b][x][1]; }
            for (int x = 4; x < 8; ++x) { c1 += g_klp[b][x][0]; c2 += g_klp[b][x][1]; }
            act += -(logf(c0 * inv_pairs) + logf(1.f - c1 * inv_pairs));
            bkg += -(logf(c2 * inv_pairs) + logf(1.f - c3 * inv_pairs));
        }
        act /= (float)NB;
        bkg /= (float)NB;
        float total = distill + act + bkg + ortho;
        float vals[5] = {total, distill, act, bkg, ortho};
        for (int i = 0; i < out_size && i < 5; ++i) out[i] = vals[i];
    }
}

// ---- launch: chain as graph roots on the capture stream (HIGH-prio via node
// priority inheritance is not available; rely on measured-good behavior: the
// chain dispatches first as roots), distill/ortho forked on LOW-prio streams. ----
extern "C" void kernel_launch(void* const* d_in, const int* in_sizes, int n_in,
                              void* d_out, int out_size) {
    const float* attn      = (const float*)d_in[0];
    const float* mu        = (const float*)d_in[1];
    const float* var       = (const float*)d_in[2];
    const float* mu_clip   = (const float*)d_in[3];
    const float* text_feat = (const float*)d_in[4];
    const float* dmask     = (const float*)d_in[5];
    float* out = (float*)d_out;

    static cudaStream_t sB = nullptr, sC = nullptr;
    static cudaEvent_t evFork = nullptr, evB = nullptr, evC = nullptr;
    if (sB == nullptr) {
        int lo, hi;
        cudaDeviceGetStreamPriorityRange(&lo, &hi);
        cudaStreamCreateWithPriority(&sB, cudaStreamNonBlocking, lo);
        cudaStreamCreateWithPriority(&sC, cudaStreamNonBlocking, lo);
        cudaEventCreateWithFlags(&evFork, cudaEventDisableTiming);
        cudaEventCreateWithFlags(&evB, cudaEventDisableTiming);
        cudaEventCreateWithFlags(&evC, cudaEventDisableTiming);
    }

    const int kl_smem = 2 * 10 * ND * (int)sizeof(float);   // 40 KB

    // fork ONLY the low-priority branches; chain kernels are graph roots on
    // the capture stream (implicit high effective priority: dispatched first).
    cudaEventRecord(evFork, 0);
    cudaStreamWaitEvent(sB, evFork, 0);
    cudaStreamWaitEvent(sC, evFork, 0);

    // low-priority persistent distill + ortho
    k_distill<<<NDB, 256, 0, sB>>>(mu, mu_clip);
    cudaEventRecord(evB, sB);
    k_ortho<<<NC, 256, 0, sC>>>(text_feat);
    cudaEventRecord(evC, sC);

    // chain directly on the capture stream (no event hop before topk)
    k_topk<<<dim3(4, NB), 512>>>(attn, dmask);
    k_kl<<<dim3(8, NB), 640, kl_smem>>>(mu, var);

    // join + finalize
    cudaStreamWaitEvent(0, evB, 0);
    cudaStreamWaitEvent(0, evC, 0);
    k_fin<<<1, 256>>>(out, out_size);
}

// round 15
// speedup vs baseline: 1.3683x; 1.3683x over previous
#include <cuda_runtime.h>
#include <math.h>

#define NB 16
#define NT 2048
#define ND 512
#define NC 20
#define KE 40
#define KH 20
#define FEPS 1e-5f
#define LN2F 0.69314718055994531f
#define NDB 740   // distill grid (5 blocks/SM on 148 SMs) — proven optimum

// ---------------- scratch (write-only slots, no zeroing needed) ----------------
__device__ int    g_idx[NB][4][KE];     // 0=easy_act,1=easy_bkg,2=hard_act,3=hard_bkg
__device__ float  g_klp[NB][8][2];      // per (b, qchunk): [0]=p hard_act, [1]=p hard_bkg
__device__ double g_dpart[NDB];         // distill per-block partials
__device__ float  g_opart[NC];          // ortho per-row partial sums of squares

// ---------------- helpers ----------------
__device__ __forceinline__ float warp_sum(float v) {
#pragma unroll
    for (int o = 16; o; o >>= 1) v += __shfl_down_sync(0xffffffffu, v, o);
    return v;
}
__device__ __forceinline__ float warp_max(float v) {
#pragma unroll
    for (int o = 16; o; o >>= 1) v = fmaxf(v, __shfl_down_sync(0xffffffffu, v, o));
    return v;
}
__device__ __forceinline__ double warp_dsum(double v) {
#pragma unroll
    for (int o = 16; o; o >>= 1) v += __shfl_down_sync(0xffffffffu, v, o);
    return v;
}
__device__ __forceinline__ unsigned long long pk2(float lo, float hi) {
    unsigned long long r;
    asm("mov.b64 %0, {%1, %2};" : "=l"(r) : "f"(lo), "f"(hi));
    return r;
}
__device__ __forceinline__ float2 upk2(unsigned long long v) {
    float2 f;
    asm("mov.b64 {%0, %1}, %2;" : "=f"(f.x), "=f"(f.y) : "l"(v));
    return f;
}
__device__ __forceinline__ unsigned long long ffma2(unsigned long long a,
                                                   unsigned long long b,
                                                   unsigned long long c) {
    unsigned long long d;
    asm("fma.rn.f32x2 %0, %1, %2, %3;" : "=l"(d) : "l"(a), "l"(b), "l"(c));
    return d;
}

// Descending radix select: bit pattern of the value at rank k (0-indexed desc).
__device__ unsigned radix_select_desc(const float* sc, int n, int k,
                                      unsigned* hist, unsigned* shc) {
    const int tid = threadIdx.x, nthr = blockDim.x;
    unsigned prefix = 0, pmask = 0;
#pragma unroll
    for (int level = 0; level < 4; ++level) {
        const int shift = 24 - 8 * level;
        for (int i = tid; i < 256; i += nthr) hist[i] = 0;
        __syncthreads();
        for (int i = tid; i < n; i += nthr) {
            unsigned u = __float_as_uint(sc[i]);
            bool ok = ((u & pmask) == prefix);
            unsigned d = ok ? ((u >> shift) & 255u) : 0x100u;
            unsigned mm = __match_any_sync(0xffffffffu, d);
            if (ok && ((tid & 31) == __ffs(mm) - 1))
                atomicAdd(&hist[d], (unsigned)__popc(mm));
        }
        __syncthreads();
        if (tid < 32) {
            const int l = tid;
            unsigned c[8]; unsigned lsum = 0;
#pragma unroll
            for (int i = 0; i < 8; ++i) { c[i] = hist[l * 8 + i]; lsum += c[i]; }
            unsigned v = lsum;
#pragma unroll
            for (int off = 1; off < 32; off <<= 1) {
                unsigned t = __shfl_down_sync(0xffffffffu, v, off);
                if (l + off < 32) v += t;
            }
            unsigned cum = v - lsum;          // elements in higher bins
            int found = -1; unsigned nk = 0;
#pragma unroll
            for (int i = 7; i >= 0; --i) {
                if (found < 0 && (unsigned)k >= cum && (unsigned)k < cum + c[i]) {
                    found = l * 8 + i; nk = (unsigned)k - cum;
                }
                cum += c[i];
            }
            if (found >= 0) { shc[0] = (unsigned)found; shc[1] = nk; }
        }
        __syncthreads();
        prefix |= shc[0] << shift;
        pmask  |= 0xFFu << shift;
        k = (int)shc[1];
        __syncthreads();
    }
    return prefix;
}

// ---------------- kernels ----------------
__global__ void __launch_bounds__(512) k_topk(const float* __restrict__ attn,
                                              const float* __restrict__ dmask) {
    __shared__ float sa[NT];
    __shared__ float ss[NT];
    __shared__ unsigned char sab[NT];
    __shared__ unsigned hist[256];
    __shared__ unsigned shc[2];
    __shared__ unsigned bm[NT / 32];
    __shared__ unsigned pfx[NT / 32];
    __shared__ float red[16];
    __shared__ int s_cnt;
    __shared__ int s_cntGE;
    __shared__ float s_maxLess;
    const int s = blockIdx.x, b = blockIdx.y, tid = threadIdx.x;
    const int warp = tid >> 5, lane = tid & 31;

    float lmax = 0.f;
    for (int t = tid; t < NT; t += 512) {
        float v = attn[b * NT + t];
        sa[t] = v;
        lmax = fmaxf(lmax, v);
    }
    lmax = warp_max(lmax);
    if (lane == 0) red[warp] = lmax;
    if (tid == 0) { s_cntGE = 0; s_maxLess = 0.f; }
    __syncthreads();
    float amax = red[0];
#pragma unroll
    for (int w = 1; w < 16; ++w) amax = fmaxf(amax, red[w]);

    if (s >= 2) {
        unsigned v1u = radix_select_desc(sa, NT, 1023, hist, shc);
        const float v1 = __uint_as_float(v1u);
        int cnt = 0; float ml = 0.f;
        for (int t = tid; t < NT; t += 512) {
            float x = sa[t];
            if (x >= v1) ++cnt; else ml = fmaxf(ml, x);
        }
#pragma unroll
        for (int o = 16; o; o >>= 1) {
            cnt += __shfl_down_sync(0xffffffffu, cnt, o);
            ml = fmaxf(ml, __shfl_down_sync(0xffffffffu, ml, o));
        }
        if (lane == 0) {
            atomicAdd(&s_cntGE, cnt);
            atomicMax((int*)&s_maxLess, __float_as_int(ml));   // floats >= 0
        }
        __syncthreads();
        float v2 = (s_cntGE >= 1025) ? v1 : s_maxLess;
        float med = 0.5f * (v1 + v2);
        for (int t = tid; t < NT; t += 512) sab[t] = (sa[t] > med) ? 1 : 0;
        __syncthreads();
    }

    for (int t = tid; t < NT; t += 512) {
        float a = sa[t];
        float v;
        if (s == 0) v = a * dmask[b * NT + t];
        else if (s == 1) v = (amax - a) * dmask[b * NT + t];
        else {
            int bm3 = (t >= 3) ? (int)sab[t - 3] : 0;
            int bm2 = (t >= 2) ? (int)sab[t - 2] : 0;
            int bm1 = (t >= 1) ? (int)sab[t - 1] : 0;
            int b0  = (int)sab[t];
            int bp1 = (t + 1 < NT) ? (int)sab[t + 1] : 0;
            int bp2 = (t + 2 < NT) ? (int)sab[t + 2] : 0;
            int bp3 = (t + 3 < NT) ? (int)sab[t + 3] : 0;
            if (s == 2) {
                int er3 = bm1 & b0 & bp1;
                int er7 = er3 & bm3 & bm2 & bp2 & bp3;
                v = a * (float)(er3 & (er7 ^ 1));
            } else {
                int dl3 = bm1 | b0 | bp1;
                int dl7 = dl3 | bm3 | bm2 | bp2 | bp3;
                v = a * (float)(dl7 & (dl3 ^ 1));
            }
        }
        ss[t] = v;
    }
    if (tid == 0) s_cnt = 0;
    for (int i = tid; i < NT / 32; i += 512) bm[i] = 0;
    __syncthreads();
    const int K = (s < 2) ? KE : KH;
    unsigned vk = radix_select_desc(ss, NT, K - 1, hist, shc);
    const float fvk = __uint_as_float(vk);
    for (int t = tid; t < NT; t += 512) {
        float v = ss[t];
        if (v > fvk) {
            int p = atomicAdd(&s_cnt, 1);
            g_idx[b][s][p] = t;
        } else if (v == fvk) {
            atomicOr(&bm[t >> 5], 1u << (t & 31));
        }
    }
    __syncthreads();
    if (tid < 32) {
        const int l = tid;
        unsigned p0 = __popc(bm[2 * l]), p1 = __popc(bm[2 * l + 1]);
        unsigned ls = p0 + p1, v = ls;
#pragma unroll
        for (int off = 1; off < 32; off <<= 1) {
            unsigned t2 = __shfl_up_sync(0xffffffffu, v, off);
            if (l >= off) v += t2;
        }
        unsigned excl = v - ls;
        pfx[2 * l] = excl;
        pfx[2 * l + 1] = excl + p0;
    }
    __syncthreads();
    const int base = s_cnt;
    const int m = K - base;
    for (int t = tid; t < NT; t += 512) {
        if (ss[t] == fvk) {
            int r = (int)(pfx[t >> 5] + __popc(bm[t >> 5] & ((1u << (t & 31)) - 1u)));
            if (r < m) g_idx[b][s][base + r] = t;
        }
    }
}

// grid (8, NB): blockIdx.x = qs*4 + qquarter (10 q-rows each). 640 thr = 20 warps.
__global__ void __launch_bounds__(640, 1) k_kl(const float* __restrict__ mu,
                                               const float* __restrict__ var) {
    extern __shared__ float sm[];
    float* r_q = sm;              // [10][ND]
    float* s_q = sm + 10 * ND;    // [10][ND]
    __shared__ float Dq[10];
    __shared__ float sAct[20], sBkg[20];
    const int qs = blockIdx.x >> 2;
    const int qq = blockIdx.x & 3;
    const int b  = blockIdx.y;
    const int warp = threadIdx.x >> 5;   // 0..19
    const int lane = threadIdx.x & 31;

    unsigned long long up[2][8], wp[2][8];
    float halfLp[2];
#pragma unroll
    for (int rr = 0; rr < 2; ++rr) {
        const int idx = g_idx[b][2 + rr][warp];
        const float4* mrow = (const float4*)(mu  + ((size_t)(b * NT + idx)) * ND);
        const float4* vrow = (const float4*)(var + ((size_t)(b * NT + idx)) * ND);
        float lsum = 0.f;
#pragma unroll
        for (int it = 0; it < 4; ++it) {
            int f = lane + it * 32;
            float4 m4 = mrow[f], v4 = vrow[f];
            v4.x += FEPS; v4.y += FEPS; v4.z += FEPS; v4.w += FEPS;
            up[rr][2 * it]     = pk2(m4.x * m4.x + v4.x, m4.y * m4.y + v4.y);
            up[rr][2 * it + 1] = pk2(m4.z * m4.z + v4.z, m4.w * m4.w + v4.w);
            wp[rr][2 * it]     = pk2(-2.f * m4.x, -2.f * m4.y);
            wp[rr][2 * it + 1] = pk2(-2.f * m4.z, -2.f * m4.w);
            lsum += __log2f(v4.x) + __log2f(v4.y) + __log2f(v4.z) + __log2f(v4.w);
        }
        lsum = warp_sum(lsum);
        halfLp[rr] = 0.5f * LN2F * __shfl_sync(0xffffffffu, lsum, 0);
    }

    if (warp < 10) {
        const int j = warp;
        const int idx = g_idx[b][qs][qq * 10 + j];
        const float4* mrow = (const float4*)(mu  + ((size_t)(b * NT + idx)) * ND);
        const float4* vrow = (const float4*)(var + ((size_t)(b * NT + idx)) * ND);
        float lsum = 0.f, asum = 0.f;
#pragma unroll
        for (int it = 0; it < 4; ++it) {
            int f = lane + it * 32;
            float4 m4 = mrow[f], v4 = vrow[f];
            v4.x += FEPS; v4.y += FEPS; v4.z += FEPS; v4.w += FEPS;
            float4 r4 = make_float4(1.f / v4.x, 1.f / v4.y, 1.f / v4.z, 1.f / v4.w);
            float4 s4 = make_float4(m4.x * r4.x, m4.y * r4.y, m4.z * r4.z, m4.w * r4.w);
            ((float4*)(r_q + j * ND))[f] = r4;
            ((float4*)(s_q + j * ND))[f] = s4;
            lsum += __log2f(v4.x) + __log2f(v4.y) + __log2f(v4.z) + __log2f(v4.w);
            asum += m4.x * s4.x + m4.y * s4.y + m4.z * s4.z + m4.w * s4.w;
        }
        float red2 = warp_sum(asum + LN2F * lsum);
        if (lane == 0) Dq[j] = 0.5f * red2;
    }
    __syncthreads();

    float accinv[2] = {0.f, 0.f};
#pragma unroll 2
    for (int j = 0; j < 10; ++j) {
        const ulonglong2* rq2 = (const ulonglong2*)(r_q + j * ND);
        const ulonglong2* sq2 = (const ulonglong2*)(s_q + j * ND);
        unsigned long long aU0 = 0, aW0 = 0, aU1 = 0, aW1 = 0;
#pragma unroll
        for (int it = 0; it < 4; ++it) {
            ulonglong2 r2 = rq2[lane + it * 32];
            ulonglong2 s2 = sq2[lane + it * 32];
            aU0 = ffma2(up[0][2 * it],     r2.x, aU0);
            aU0 = ffma2(up[0][2 * it + 1], r2.y, aU0);
            aW0 = ffma2(wp[0][2 * it],     s2.x, aW0);
            aW0 = ffma2(wp[0][2 * it + 1], s2.y, aW0);
            aU1 = ffma2(up[1][2 * it],     r2.x, aU1);
            aU1 = ffma2(up[1][2 * it + 1], r2.y, aU1);
            aW1 = ffma2(wp[1][2 * it],     s2.x, aW1);
            aW1 = ffma2(wp[1][2 * it + 1], s2.y, aW1);
        }
        float2 u0 = upk2(aU0), w0 = upk2(aW0);
        float2 u1 = upk2(aU1), w1 = upk2(aW1);
        float v0 = u0.x + u0.y + w0.x + w0.y;
        float v1 = u1.x + u1.y + w1.x + w1.y;
#pragma unroll
        for (int o = 16; o; o >>= 1) {
            v0 += __shfl_down_sync(0xffffffffu, v0, o);
            v1 += __shfl_down_sync(0xffffffffu, v1, o);
        }
        if (lane == 0) {
            float d0 = 0.5f * v0 + Dq[j] - halfLp[0] - 0.5f * (float)ND;
            float d1 = 0.5f * v1 + Dq[j] - halfLp[1] - 0.5f * (float)ND;
            accinv[0] += 1.f / (d0 + 1.f);
            accinv[1] += 1.f / (d1 + 1.f);
        }
    }
    if (lane == 0) { sAct[warp] = accinv[0]; sBkg[warp] = accinv[1]; }
    __syncthreads();
    if (warp == 0) {
        float va = (lane < 20) ? sAct[lane] : 0.f;
        float vb = (lane < 20) ? sBkg[lane] : 0.f;
        va = warp_sum(va);
        vb = warp_sum(vb);
        if (lane == 0) {
            g_klp[b][blockIdx.x][0] = va;
            g_klp[b][blockIdx.x][1] = vb;
        }
    }
}

// persistent grid-stride distill (grid=NDB, 5 blocks/SM).
// Warp processes row pairs (row, row+16384).
__global__ void __launch_bounds__(256) k_distill(const float* __restrict__ mu,
                                                 const float* __restrict__ mc) {
    const int lane = threadIdx.x & 31;
    const int wib  = threadIdx.x >> 5;
    const int gw   = blockIdx.x * 8 + wib;
    const int nw   = gridDim.x * 8;
    double local = 0.0;
    for (int row = gw; row < 16384; row += nw) {
        const size_t r0 = (size_t)row * ND;
        const size_t r1 = (size_t)(row + 16384) * ND;
        const float4* a0 = (const float4*)(mu + r0);
        const float4* c0 = (const float4*)(mc + r0);
        const float4* a1 = (const float4*)(mu + r1);
        const float4* c1 = (const float4*)(mc + r1);
        float d0 = 0.f, p0 = 0.f, q0 = 0.f;
        float d1 = 0.f, p1 = 0.f, q1 = 0.f;
#pragma unroll
        for (int it = 0; it < 4; ++it) {
            int f = lane + it * 32;
            float4 x0 = __ldcs(&a0[f]);
            float4 y0 = __ldcs(&c0[f]);
            float4 x1 = __ldcs(&a1[f]);
            float4 y1 = __ldcs(&c1[f]);
            d0 += x0.x * y0.x + x0.y * y0.y + x0.z * y0.z + x0.w * y0.w;
            p0 += x0.x * x0.x + x0.y * x0.y + x0.z * x0.z + x0.w * x0.w;
            q0 += y0.x * y0.x + y0.y * y0.y + y0.z * y0.z + y0.w * y0.w;
            d1 += x1.x * y1.x + x1.y * y1.y + x1.z * y1.z + x1.w * y1.w;
            p1 += x1.x * x1.x + x1.y * x1.y + x1.z * x1.z + x1.w * x1.w;
            q1 += y1.x * y1.x + y1.y * y1.y + y1.z * y1.z + y1.w * y1.w;
        }
#pragma unroll
        for (int o = 16; o; o >>= 1) {
            d0 += __shfl_down_sync(0xffffffffu, d0, o);
            p0 += __shfl_down_sync(0xffffffffu, p0, o);
            q0 += __shfl_down_sync(0xffffffffu, q0, o);
            d1 += __shfl_down_sync(0xffffffffu, d1, o);
            p1 += __shfl_down_sync(0xffffffffu, p1, o);
            q1 += __shfl_down_sync(0xffffffffu, q1, o);
        }
        if (lane == 0) {
            float s0 = d0 / (fmaxf(sqrtf(p0), 1e-12f) * fmaxf(sqrtf(q0), 1e-12f));
            float s1 = d1 / (fmaxf(sqrtf(p1), 1e-12f) * fmaxf(sqrtf(q1), 1e-12f));
            local += (double)((s0 + 1.f) * 0.5f) + (double)((s1 + 1.f) * 0.5f);
        }
    }
    __shared__ double bs[8];
    if (lane == 0) bs[wib] = local;
    __syncthreads();
    if (threadIdx.x == 0) {
        double s = 0.0;
        for (int w = 0; w < 8; ++w) s += bs[w];
        g_dpart[blockIdx.x] = s;
    }
}

// grid 20, 256 thr: block i computes sum_j (sim(i,j) - delta_ij)^2 -> g_opart[i]
__global__ void __launch_bounds__(256) k_ortho(const float* __restrict__ tf) {
    __shared__ float e[NC * ND];
    __shared__ float inv_n[NC];
    __shared__ float part[8];
    const int i = blockIdx.x;
    const int tid = threadIdx.x;
    const int warp = tid >> 5, lane = tid & 31;
    for (int k = tid; k < NC * (ND / 4); k += 256)
        ((float4*)e)[k] = ((const float4*)tf)[k];
    __syncthreads();
    for (int r = warp; r < NC; r += 8) {
        const float4* er = (const float4*)(e + r * ND);
        float4 acc = make_float4(0.f, 0.f, 0.f, 0.f);
#pragma unroll
        for (int it = 0; it < 4; ++it) {
            float4 v = er[lane + it * 32];
            acc.x += v.x * v.x; acc.y += v.y * v.y;
            acc.z += v.z * v.z; acc.w += v.w * v.w;
        }
        float s = warp_sum(acc.x + acc.y + acc.z + acc.w);
        if (lane == 0) inv_n[r] = 1.f / fmaxf(sqrtf(s), 1e-12f);
    }
    __syncthreads();
    const float4* ei = (const float4*)(e + i * ND);
    float accp = 0.f;
    for (int j = warp; j < NC; j += 8) {
        const float4* ej = (const float4*)(e + j * ND);
        float4 acc = make_float4(0.f, 0.f, 0.f, 0.f);
#pragma unroll
        for (int it = 0; it < 4; ++it) {
            int f = lane + it * 32;
            float4 x = ei[f], y = ej[f];
            acc.x += x.x * y.x; acc.y += x.y * y.y;
            acc.z += x.z * y.z; acc.w += x.w * y.w;
        }
        float s = warp_sum(acc.x + acc.y + acc.z + acc.w);
        if (lane == 0) {
            float m = s * inv_n[i] * inv_n[j] - ((i == j) ? 1.f : 0.f);
            accp += m * m;
        }
    }
    if (lane == 0) part[warp] = accp;
    __syncthreads();
    if (tid == 0) {
        float s = 0.f;
        for (int w = 0; w < 8; ++w) s += part[w];
        g_opart[i] = s;
    }
}

// single block scalar finalization
__global__ void __launch_bounds__(256) k_fin(float* __restrict__ out, int out_size) {
    __shared__ double dpartial[8];
    const int tid = threadIdx.x;
    const int warp = tid >> 5, lane = tid & 31;
    double dl = 0.0;
#pragma unroll
    for (int i = 0; i < 3; ++i) {
        int idx = tid + i * 256;
        if (idx < NDB) dl += g_dpart[idx];
    }
    dl = warp_dsum(dl);
    if (lane == 0) dpartial[warp] = dl;
    __syncthreads();
    if (tid == 0) {
        double ds = 0.0;
        for (int w = 0; w < 8; ++w) ds += dpartial[w];
        float distill = -logf((float)(ds / (double)(NB * NT)));
        float os = 0.f;
        for (int i = 0; i < NC; ++i) os += g_opart[i];
        float ortho = sqrtf(os);
        const float inv_pairs = 1.f / (float)(KH * KE);
        float act = 0.f, bkg = 0.f;
        for (int b = 0; b < NB; ++b) {
            float c0 = 0.f, c1 = 0.f, c2 = 0.f, c3 = 0.f;
            for (int x = 0; x < 4; ++x) { c0 += g_klp[b][x][0]; c3 += g_klp[b][x][1]; }
            for (int x = 4; x < 8; ++x) { c1 += g_klp[b][x][0]; c2 += g_klp[b][x][1]; }
            act += -(logf(c0 * inv_pairs) + logf(1.f - c1 * inv_pairs));
            bkg += -(logf(c2 * inv_pairs) + logf(1.f - c3 * inv_pairs));
        }
        act /= (float)NB;
        bkg /= (float)NB;
        float total = distill + act + bkg + ortho;
        float vals[5] = {total, distill, act, bkg, ortho};
        for (int i = 0; i < out_size && i < 5; ++i) out[i] = vals[i];
    }
}

// ---- launch: priority fork (chain HIGH | distill LOW | ortho LOW), join, fin ----
extern "C" void kernel_launch(void* const* d_in, const int* in_sizes, int n_in,
                              void* d_out, int out_size) {
    const float* attn      = (const float*)d_in[0];
    const float* mu        = (const float*)d_in[1];
    const float* var       = (const float*)d_in[2];
    const float* mu_clip   = (const float*)d_in[3];
    const float* text_feat = (const float*)d_in[4];
    const float* dmask     = (const float*)d_in[5];
    float* out = (float*)d_out;

    static cudaStream_t sA = nullptr, sB = nullptr, sC = nullptr;
    static cudaEvent_t evFork = nullptr, evA = nullptr, evB = nullptr, evC = nullptr;
    if (sA == nullptr) {
        int lo, hi;
        cudaDeviceGetStreamPriorityRange(&lo, &hi);  // hi = highest priority
        cudaStreamCreateWithPriority(&sA, cudaStreamNonBlocking, hi);
        cudaStreamCreateWithPriority(&sB, cudaStreamNonBlocking, lo);
        cudaStreamCreateWithPriority(&sC, cudaStreamNonBlocking, lo);
        cudaEventCreateWithFlags(&evFork, cudaEventDisableTiming);
        cudaEventCreateWithFlags(&evA, cudaEventDisableTiming);
        cudaEventCreateWithFlags(&evB, cudaEventDisableTiming);
        cudaEventCreateWithFlags(&evC, cudaEventDisableTiming);
    }

    const int kl_smem = 2 * 10 * ND * (int)sizeof(float);   // 40 KB

    cudaEventRecord(evFork, 0);
    cudaStreamWaitEvent(sA, evFork, 0);
    cudaStreamWaitEvent(sB, evFork, 0);
    cudaStreamWaitEvent(sC, evFork, 0);

    // high-priority chain
    k_topk<<<dim3(4, NB), 512, 0, sA>>>(attn, dmask);
    k_kl<<<dim3(8, NB), 640, kl_smem, sA>>>(mu, var);
    cudaEventRecord(evA, sA);

    // low-priority persistent distill + ortho
    k_distill<<<NDB, 256, 0, sB>>>(mu, mu_clip);
    cudaEventRecord(evB, sB);
    k_ortho<<<NC, 256, 0, sC>>>(text_feat);
    cudaEventRecord(evC, sC);

    cudaStreamWaitEvent(0, evA, 0);
    cudaStreamWaitEvent(0, evB, 0);
    cudaStreamWaitEvent(0, evC, 0);
    k_fin<<<1, 256>>>(out, out_size);
}